// round 15
// baseline (speedup 1.0000x reference)
#include <cuda_runtime.h>
#include <cuda_fp16.h>
#include <cstdint>
#include <math.h>

#define NH    16
#define DH    64
#define LSEQ  2048
#define NB    2
#define INNER 1024
#define QK_SCALE 0.125f

// Scratch (__device__ globals; allocation-free rule) — fp32 proven pipeline.
__device__ float g_q[(size_t)NB*NH*LSEQ*DH];   // [b,h,l,dh]
__device__ float g_k[(size_t)NB*NH*LSEQ*DH];
__device__ float g_v[(size_t)NB*NH*LSEQ*DH];
__device__ float g_z[(size_t)NB*LSEQ*INNER];   // [b,l,h*dh]

// ---------------------------------------------------------------------------
// Helpers (sm_80-baseline; safe on plain sm_103 target). NO cp.async.
// ---------------------------------------------------------------------------
__device__ __forceinline__ void mma16(float d[4], const uint32_t a[4],
                                      const uint32_t b[2]) {
    asm volatile(
        "mma.sync.aligned.m16n8k16.row.col.f32.f16.f16.f32 "
        "{%0,%1,%2,%3}, {%4,%5,%6,%7}, {%8,%9}, {%0,%1,%2,%3};"
        : "+f"(d[0]), "+f"(d[1]), "+f"(d[2]), "+f"(d[3])
        : "r"(a[0]), "r"(a[1]), "r"(a[2]), "r"(a[3]),
          "r"(b[0]), "r"(b[1]));
}
__device__ __forceinline__ uint32_t pack2(float lo, float hi) {
    __half2 h = __floats2half2_rn(lo, hi);
    return *(uint32_t*)&h;
}

// ---------------------------------------------------------------------------
// fp16 GEMM, warp M-tile = 32 rows (2 subtiles sharing B fragments).
// C[4096][Ncols] = A[4096][1024] @ W[1024][Ncols] (W native layout).
// Block 128m x 64n, 128 threads = 4 warps; K-tile 64 (16 iterations).
// mode 0: scatter C to q/k/v (fp32). mode 1: C + bias -> out.
// ---------------------------------------------------------------------------
__global__ __launch_bounds__(128) void gemm_w32(const float* __restrict__ A,
                                                const float* __restrict__ W,
                                                const float* __restrict__ bias,
                                                float* __restrict__ outp,
                                                int Ncols, int mode)
{
    extern __shared__ uint32_t sh[];
    uint32_t* As2 = sh;              // [128 m][36] u32 (32 kpairs + pad)
    uint32_t* Bs2 = sh + 128 * 36;   // [32 kpair][68] u32 (64 n + pad)

    const int tid  = threadIdx.x;
    const int lane = tid & 31;
    const int w    = tid >> 5;      // 0..3
    const int g    = lane >> 2;
    const int t    = lane & 3;
    const int m0   = blockIdx.y * 128;
    const int n0   = blockIdx.x * 64;
    const int rw   = w * 32;        // warp's 32-row slab

    float acc[2][8][4];
    #pragma unroll
    for (int s = 0; s < 2; s++)
        #pragma unroll
        for (int j = 0; j < 8; j++)
            #pragma unroll
            for (int r = 0; r < 4; r++) acc[s][j][r] = 0.f;

    #pragma unroll 1
    for (int kt = 0; kt < 16; kt++) {
        __syncthreads();
        // Stage A 128x64 (fp32 -> half2 pairs along k): 2048 float4
        #pragma unroll
        for (int i = 0; i < 16; i++) {
            int idx = tid + 128 * i;
            int r = idx >> 4, c = (idx & 15) * 4;
            float4 a4 = *(const float4*)&A[(size_t)(m0 + r) * 1024 + kt * 64 + c];
            uint2 p = { pack2(a4.x, a4.y), pack2(a4.z, a4.w) };
            *(uint2*)&As2[r * 36 + (c >> 1)] = p;
        }
        // Stage B 64x64: pack k-rows 2kp,2kp+1 into half2: 512 uint4
        #pragma unroll
        for (int i = 0; i < 4; i++) {
            int idx = tid + 128 * i;
            int kp = idx >> 4, nc = (idx & 15) * 4;
            const float* wr = W + (size_t)(kt * 64 + 2 * kp) * Ncols + n0 + nc;
            float4 e = *(const float4*)wr;
            float4 o = *(const float4*)(wr + Ncols);
            uint4 p = { pack2(e.x, o.x), pack2(e.y, o.y),
                        pack2(e.z, o.z), pack2(e.w, o.w) };
            *(uint4*)&Bs2[kp * 68 + nc] = p;
        }
        __syncthreads();

        #pragma unroll
        for (int ks = 0; ks < 4; ks++) {
            uint32_t af[2][4];
            #pragma unroll
            for (int s = 0; s < 2; s++) {
                int row = rw + s * 16;
                af[s][0] = As2[(row + g) * 36 + ks * 8 + t];
                af[s][1] = As2[(row + g + 8) * 36 + ks * 8 + t];
                af[s][2] = As2[(row + g) * 36 + ks * 8 + t + 4];
                af[s][3] = As2[(row + g + 8) * 36 + ks * 8 + t + 4];
            }
            #pragma unroll
            for (int j = 0; j < 8; j++) {
                uint32_t bf[2];
                bf[0] = Bs2[(ks * 8 + t) * 68 + j * 8 + g];
                bf[1] = Bs2[(ks * 8 + t + 4) * 68 + j * 8 + g];
                mma16(acc[0][j], af[0], bf);
                mma16(acc[1][j], af[1], bf);
            }
        }
    }

    #pragma unroll
    for (int s = 0; s < 2; s++) {
        int r_lo = m0 + rw + s * 16 + g;
        int r_hi = r_lo + 8;
        #pragma unroll
        for (int j = 0; j < 8; j++) {
            int n = n0 + j * 8 + 2 * t;
            if (mode == 1) {
                float2 o0 = { acc[s][j][0] + bias[n], acc[s][j][1] + bias[n + 1] };
                float2 o1 = { acc[s][j][2] + bias[n], acc[s][j][3] + bias[n + 1] };
                *(float2*)&outp[(size_t)r_lo * 1024 + n] = o0;
                *(float2*)&outp[(size_t)r_hi * 1024 + n] = o1;
            } else {
                int three = n >> 10, rem = n & 1023, hh = rem >> 6, dd = rem & 63;
                float* base = (three == 0) ? g_q : (three == 1) ? g_k : g_v;
                int bb_lo = r_lo >> 11, ll_lo = r_lo & 2047;
                int bb_hi = r_hi >> 11, ll_hi = r_hi & 2047;
                float2 o0 = { acc[s][j][0], acc[s][j][1] };
                float2 o1 = { acc[s][j][2], acc[s][j][3] };
                *(float2*)&base[(((size_t)(bb_lo * NH + hh) * LSEQ) + ll_lo) * DH + dd] = o0;
                *(float2*)&base[(((size_t)(bb_hi * NH + hh) * LSEQ) + ll_hi) * DH + dd] = o1;
            }
        }
    }
}

// ---------------------------------------------------------------------------
// Attention: warp M-tile = 32 q-rows (2 subtiles sharing K/V fragments).
// BM=128, 128 threads = 4 warps. Mask via direct LDG at fragment coords.
// No-max exact softmax: p=exp(s); z=(p*mask)@V / (sum(p*mask)+eps*sum(p)).
// ---------------------------------------------------------------------------
__global__ __launch_bounds__(128) void attn_w32(const float* __restrict__ mask,
                                                float* __restrict__ z)
{
    extern __shared__ uint32_t sh[];
    uint32_t* Ks2 = sh;                      // [64 seq][36] half2 along dh
    uint32_t* Vs2 = Ks2 + 64 * 36;           // [32 seqpair][68] half2 = seq pair
    uint32_t* Ps2 = Vs2 + 32 * 68;           // [128 q][36] half2 along seq

    const int tid  = threadIdx.x;
    const int lane = tid & 31;
    const int w    = tid >> 5;               // 0..3
    const int g    = lane >> 2;
    const int t    = lane & 3;
    const int qb   = blockIdx.x;
    const int bh   = blockIdx.y;
    const int bb   = bh >> 4, hh = bh & 15;
    const int q0   = qb * 128;
    const int rw   = w * 32;                 // warp's 32-row slab

    const float* qp = g_q + ((size_t)bh * LSEQ + q0) * DH;
    const float* kp = g_k + (size_t)bh * LSEQ * DH;
    const float* vp = g_v + (size_t)bh * LSEQ * DH;
    const float* mrow[2][2];
    #pragma unroll
    for (int s = 0; s < 2; s++) {
        mrow[s][0] = mask + ((size_t)bb * LSEQ + q0 + rw + s * 16 + g) * LSEQ;
        mrow[s][1] = mrow[s][0] + (size_t)8 * LSEQ;
    }

    // Q fragments direct from fp32 gmem, scale folded
    uint32_t qa[2][4][4];
    #pragma unroll
    for (int s = 0; s < 2; s++) {
        #pragma unroll
        for (int ks = 0; ks < 4; ks++) {
            const float* q_lo = qp + (rw + s * 16 + g) * 64 + ks * 16 + 2 * t;
            const float* q_hi = q_lo + 8 * 64;
            float2 a = *(const float2*)q_lo;
            float2 b = *(const float2*)q_hi;
            float2 c = *(const float2*)(q_lo + 8);
            float2 d = *(const float2*)(q_hi + 8);
            qa[s][ks][0] = pack2(QK_SCALE * a.x, QK_SCALE * a.y);
            qa[s][ks][1] = pack2(QK_SCALE * b.x, QK_SCALE * b.y);
            qa[s][ks][2] = pack2(QK_SCALE * c.x, QK_SCALE * c.y);
            qa[s][ks][3] = pack2(QK_SCALE * d.x, QK_SCALE * d.y);
        }
    }

    float zacc[2][8][4];
    #pragma unroll
    for (int s = 0; s < 2; s++)
        #pragma unroll
        for (int j = 0; j < 8; j++)
            #pragma unroll
            for (int r = 0; r < 4; r++) zacc[s][j][r] = 0.f;
    float sa[2][2] = {{0.f, 0.f}, {0.f, 0.f}};   // [sub][lo/hi]
    float sk[2][2] = {{0.f, 0.f}, {0.f, 0.f}};

    #pragma unroll 1
    for (int jt = 0; jt < LSEQ / 64; jt++) {
        __syncthreads();   // all warps done reading Ks2/Vs2 from prior iter
        // Stage K 64x64 (fp32 -> half2 along dh): 1024 float4, 128 threads
        #pragma unroll
        for (int i = 0; i < 8; i++) {
            int idx = tid + 128 * i;
            int r = idx >> 4, c = (idx & 15) * 4;
            float4 k4 = *(const float4*)&kp[(size_t)(jt * 64 + r) * 64 + c];
            uint2 p = { pack2(k4.x, k4.y), pack2(k4.z, k4.w) };
            *(uint2*)&Ks2[r * 36 + (c >> 1)] = p;
        }
        // Stage V 64x64: pack seq rows 2s,2s+1 into half2: 512 entries
        #pragma unroll
        for (int i = 0; i < 4; i++) {
            int idx = tid + 128 * i;
            int sp = idx >> 4, d = (idx & 15) * 4;
            const float* vr = vp + (size_t)(jt * 64 + 2 * sp) * 64 + d;
            float4 e = *(const float4*)vr;
            float4 o = *(const float4*)(vr + 64);
            uint4 p = { pack2(e.x, o.x), pack2(e.y, o.y),
                        pack2(e.z, o.z), pack2(e.w, o.w) };
            *(uint4*)&Vs2[sp * 68 + d] = p;
        }
        __syncthreads();

        // S = Q K^T (scaled); K fragments shared across both subtiles
        float sacc[2][8][4];
        #pragma unroll
        for (int s = 0; s < 2; s++)
            #pragma unroll
            for (int j = 0; j < 8; j++)
                #pragma unroll
                for (int r = 0; r < 4; r++) sacc[s][j][r] = 0.f;
        #pragma unroll
        for (int ks = 0; ks < 4; ks++) {
            #pragma unroll
            for (int j = 0; j < 8; j++) {
                uint32_t bf[2];
                bf[0] = Ks2[(j * 8 + g) * 36 + ks * 8 + t];
                bf[1] = Ks2[(j * 8 + g) * 36 + ks * 8 + t + 4];
                mma16(sacc[0][j], qa[0][ks], bf);
                mma16(sacc[1][j], qa[1][ks], bf);
            }
        }

        // exp + mask (direct LDG) + row sums; write P (half2 along seq)
        #pragma unroll
        for (int s = 0; s < 2; s++) {
            #pragma unroll
            for (int j = 0; j < 8; j++) {
                float p0 = __expf(sacc[s][j][0]);
                float p1 = __expf(sacc[s][j][1]);
                float p2 = __expf(sacc[s][j][2]);
                float p3 = __expf(sacc[s][j][3]);
                float2 mlo = *(const float2*)&mrow[s][0][jt * 64 + j * 8 + 2 * t];
                float2 mhi = *(const float2*)&mrow[s][1][jt * 64 + j * 8 + 2 * t];
                float w0 = p0 * mlo.x, w1 = p1 * mlo.y;
                float w2 = p2 * mhi.x, w3 = p3 * mhi.y;
                sa[s][0] += p0 + p1;  sa[s][1] += p2 + p3;
                sk[s][0] += w0 + w1;  sk[s][1] += w2 + w3;
                Ps2[(rw + s * 16 + g) * 36 + j * 4 + t]     = pack2(w0, w1);
                Ps2[(rw + s * 16 + g + 8) * 36 + j * 4 + t] = pack2(w2, w3);
            }
        }
        __syncwarp();   // P rows are warp-private

        // zacc += P @ V; V fragments shared across both subtiles
        #pragma unroll
        for (int ks = 0; ks < 4; ks++) {
            uint32_t pa4[2][4];
            #pragma unroll
            for (int s = 0; s < 2; s++) {
                int row = rw + s * 16;
                pa4[s][0] = Ps2[(row + g) * 36 + ks * 8 + t];
                pa4[s][1] = Ps2[(row + g + 8) * 36 + ks * 8 + t];
                pa4[s][2] = Ps2[(row + g) * 36 + ks * 8 + t + 4];
                pa4[s][3] = Ps2[(row + g + 8) * 36 + ks * 8 + t + 4];
            }
            #pragma unroll
            for (int j = 0; j < 8; j++) {
                uint32_t bf[2];
                bf[0] = Vs2[(ks * 8 + t) * 68 + j * 8 + g];
                bf[1] = Vs2[(ks * 8 + t + 4) * 68 + j * 8 + g];
                mma16(zacc[0][j], pa4[0], bf);
                mma16(zacc[1][j], pa4[1], bf);
            }
        }
    }

    #pragma unroll
    for (int s = 0; s < 2; s++) {
        #pragma unroll
        for (int d = 1; d <= 2; d <<= 1) {
            sa[s][0] += __shfl_xor_sync(0xffffffffu, sa[s][0], d);
            sa[s][1] += __shfl_xor_sync(0xffffffffu, sa[s][1], d);
            sk[s][0] += __shfl_xor_sync(0xffffffffu, sk[s][0], d);
            sk[s][1] += __shfl_xor_sync(0xffffffffu, sk[s][1], d);
        }
        float inv_lo = 1.f / (sk[s][0] + 1e-10f * sa[s][0]);
        float inv_hi = 1.f / (sk[s][1] + 1e-10f * sa[s][1]);

        size_t row_lo = (size_t)bb * LSEQ + q0 + rw + s * 16 + g;
        size_t row_hi = row_lo + 8;
        #pragma unroll
        for (int j = 0; j < 8; j++) {
            int dh = hh * 64 + j * 8 + 2 * t;
            float2 o0 = { zacc[s][j][0] * inv_lo, zacc[s][j][1] * inv_lo };
            float2 o1 = { zacc[s][j][2] * inv_hi, zacc[s][j][3] * inv_hi };
            *(float2*)&z[row_lo * INNER + dh] = o0;
            *(float2*)&z[row_hi * INNER + dh] = o1;
        }
    }
}

// ---------------------------------------------------------------------------
extern "C" void kernel_launch(void* const* d_in, const int* in_sizes, int n_in,
                              void* d_out, int out_size)
{
    const float* x     = (const float*)d_in[0];  // [2,2048,1024]
    const float* mask  = (const float*)d_in[1];  // [2,2048,2048]
    const float* W_qkv = (const float*)d_in[2];  // [1024,3072]
    const float* W_out = (const float*)d_in[3];  // [1024,1024]
    const float* b_out = (const float*)d_in[4];  // [1024]
    float* out = (float*)d_out;

    const int gemm_smem = (128 * 36 + 32 * 68) * 4;   // 27136 B
    cudaFuncSetAttribute(gemm_w32, cudaFuncAttributeMaxDynamicSharedMemorySize, gemm_smem);

    // QKV projection -> fp32 q/k/v (W in native [k][n] layout)
    gemm_w32<<<dim3(3072 / 64, 4096 / 128), 128, gemm_smem>>>(
        x, W_qkv, nullptr, nullptr, 3072, 0);

    // Attention (BM=128, 4 warps x 32 rows, mask via direct LDG)
    const int attn_smem = (64 * 36 + 32 * 68 + 128 * 36) * 4;  // 36352 B
    cudaFuncSetAttribute(attn_w32, cudaFuncAttributeMaxDynamicSharedMemorySize, attn_smem);
    attn_w32<<<dim3(LSEQ / 128, NB * NH), 128, attn_smem>>>(mask, g_z);

    // Output projection + bias
    gemm_w32<<<dim3(1024 / 64, 4096 / 128), 128, gemm_smem>>>(
        g_z, W_out, b_out, out, 1024, 1);
}